// round 11
// baseline (speedup 1.0000x reference)
#include <cuda_runtime.h>
#include <cstdint>

#define DIM 85
#define B_ROWS 262144
#define TROWS 32
#define NWARPS_C 8                 // consumer warps
#define THREADS 288                // 8 consumers + 1 producer warp
#define NT (B_ROWS / TROWS)        // 8192 tiles
#define GRID 296                   // 2 persistent CTAs per SM
#define STAGES 4
#define TILE_F (TROWS * DIM)       // 2720 floats per array
#define TILE_B (TILE_F * 4)        // 10880 bytes
#define STAGE_B (2 * TILE_B)       // 21760 bytes (in + tg)

#define OFF_FULL  0                                  // 4 x 8 B
#define OFF_EMPTY 32                                 // 4 x 8 B
#define OFF_DATA  64
#define SMEM_TOTAL (OFF_DATA + STAGES * STAGE_B)     // 87104 B -> 2 CTAs/SM

__device__ float g_partials[GRID];
__device__ int   g_count = 0;

__device__ __forceinline__ void mbar_init(uint32_t mbar, uint32_t cnt) {
    asm volatile("mbarrier.init.shared.b64 [%0], %1;" :: "r"(mbar), "r"(cnt) : "memory");
}
__device__ __forceinline__ void mbar_expect_tx(uint32_t mbar, uint32_t bytes) {
    asm volatile("mbarrier.arrive.expect_tx.shared.b64 _, [%0], %1;"
                 :: "r"(mbar), "r"(bytes) : "memory");
}
__device__ __forceinline__ void mbar_arrive(uint32_t mbar) {
    asm volatile("mbarrier.arrive.release.cta.shared::cta.b64 _, [%0];"
                 :: "r"(mbar) : "memory");
}
__device__ __forceinline__ void mbar_wait(uint32_t mbar, uint32_t parity) {
    asm volatile(
        "{\n\t"
        ".reg .pred P;\n\t"
        "W_%=:\n\t"
        "mbarrier.try_wait.parity.acquire.cta.shared::cta.b64 P, [%0], %1, 0x989680;\n\t"
        "@P bra D_%=;\n\t"
        "bra W_%=;\n\t"
        "D_%=:\n\t"
        "}" :: "r"(mbar), "r"(parity) : "memory");
}
__device__ __forceinline__ void bulk_g2s(uint32_t dst, const void* src,
                                         uint32_t bytes, uint32_t mbar) {
    asm volatile(
        "cp.async.bulk.shared::cta.global.mbarrier::complete_tx::bytes [%0], [%1], %2, [%3];"
        :: "r"(dst), "l"(src), "r"(bytes), "r"(mbar) : "memory");
}

__global__ __launch_bounds__(THREADS)
void qfd_ws(const float* __restrict__ in, const float* __restrict__ tg,
            float* __restrict__ out)
{
    extern __shared__ __align__(16) unsigned char smraw[];
    __shared__ float warp_part[THREADS / 32];
    __shared__ bool  s_is_last;

    const int tid  = threadIdx.x;
    const int wid  = tid >> 5;
    const int lane = tid & 31;

    const uint32_t full0  = (uint32_t)__cvta_generic_to_shared(smraw + OFF_FULL);
    const uint32_t empty0 = (uint32_t)__cvta_generic_to_shared(smraw + OFF_EMPTY);
    const uint32_t data_s = (uint32_t)__cvta_generic_to_shared(smraw + OFF_DATA);

    if (tid == 0) {
#pragma unroll
        for (int s = 0; s < STAGES; s++) {
            mbar_init(full0  + 8u * s, 1);
            mbar_init(empty0 + 8u * s, NWARPS_C);
        }
        asm volatile("fence.proxy.async.shared::cta;" ::: "memory");
    }
    __syncthreads();

    const int t0 = blockIdx.x;
    float acc = 0.0f;

    if (wid == NWARPS_C) {
        // ================= producer warp (single thread) =================
        if (lane == 0) {
            int it = 0;
            for (int t = t0; t < NT; t += GRID, it++) {
                const int s = it & (STAGES - 1);
                const int r = it >> 2;                     // refill round
                if (r > 0)
                    mbar_wait(empty0 + 8u * s, (uint32_t)((r - 1) & 1));
                uint32_t mb = full0 + 8u * s;
                uint32_t ds = data_s + (uint32_t)(s * STAGE_B);
                mbar_expect_tx(mb, STAGE_B);
                bulk_g2s(ds,          in + (size_t)t * TILE_F, TILE_B, mb);
                bulk_g2s(ds + TILE_B, tg + (size_t)t * TILE_F, TILE_B, mb);
            }
        }
    } else {
        // ================= consumer warps =================
        const int row = 4 * wid + (lane >> 3);             // warp-private rows
        const int l8  = lane & 7;
        const int len  = (l8 < 5) ? 11 : 10;
        const int kbeg = 11 * l8 - ((l8 > 5) ? (l8 - 5) : 0);   // 0,11,22,33,44,55,65,75
        const float fkend = (float)(kbeg + len);
        const int roff = row * DIM + kbeg;

        int it = 0;
        for (int t = t0; t < NT; t += GRID, it++) {
            const int s  = it & (STAGES - 1);
            const int ph = (it >> 2) & 1;
            mbar_wait(full0 + 8u * s, (uint32_t)ph);

            const float* in_sm = (const float*)(smraw + OFF_DATA + s * STAGE_B);
            const float* tg_sm = (const float*)(smraw + OFF_DATA + s * STAGE_B + TILE_B);
            const float* ri = in_sm + roff;
            const float* rt = tg_sm + roff;

            // lane-local scan:  U += d*R ; C += d ; R += C
            float C = 0.0f, R = 0.0f, U = 0.0f;
#pragma unroll
            for (int k = 0; k < 11; k++) {
                if (k < len) {
                    float d = fabsf(ri[k] - rt[k]);
                    U = fmaf(d, R, U);
                    C += d;
                    R += C;
                }
            }
            // done reading stage s
            if (l8 == 0 && (lane >> 3) == 0)
                ;   // placeholder (arrive moved below after merge uses registers only)
            float P = C;
            float T = fmaf(fkend, C, -R);                  // absolute moment

            // signal consumption now — everything below is register-only
            if (lane == 0)
                mbar_arrive(empty0 + 8u * s);

            // ordered tree merge over 8 lanes of the row (masks 1,2,4)
#pragma unroll
            for (int m = 1; m < 8; m <<= 1) {
                float Po = __shfl_xor_sync(0xffffffffu, P, m);
                float To = __shfl_xor_sync(0xffffffffu, T, m);
                float Uo = __shfl_xor_sync(0xffffffffu, U, m);
                float c  = fmaf(P, To, -(T * Po));         // P_A T_B - T_A P_B (A=low)
                U += Uo + ((l8 & m) ? -c : c);
                P += Po;
                T += To;
            }
            if (l8 == 0)
                acc += fmaf(P, P, -(2.0f / (float)DIM) * U);
        }
    }

    // ---- deterministic block reduce over all 9 warps ----
    for (int o = 16; o; o >>= 1)
        acc += __shfl_down_sync(0xffffffffu, acc, o);
    if (lane == 0)
        warp_part[wid] = acc;
    __syncthreads();

    if (tid == 0) {
        float s = 0.0f;
#pragma unroll
        for (int i = 0; i < THREADS / 32; i++)
            s += warp_part[i];
        g_partials[blockIdx.x] = s;
        __threadfence();
        int old = atomicAdd(&g_count, 1);
        s_is_last = (old == GRID - 1);
    }
    __syncthreads();

    // ---- last-arriving block: final deterministic reduce in double ----
    if (s_is_last) {
        __shared__ double sd[THREADS];
        double a = 0.0;
#pragma unroll
        for (int j = 0; j < (GRID + THREADS - 1) / THREADS; j++) {
            int i = tid + j * THREADS;
            if (i < GRID) a += (double)g_partials[i];
        }
        sd[tid] = a;
        __syncthreads();
        for (int o = 256; o; o >>= 1) {           // 288 threads: fold 256..287 first
            if (tid < o && tid + o < THREADS) sd[tid] += sd[tid + o];
            __syncthreads();
        }
        if (tid == 0) {
            out[0] = (float)(0.1 * sd[0]);
            g_count = 0;                          // self-reset for next replay
        }
    }
}

extern "C" void kernel_launch(void* const* d_in, const int* in_sizes, int n_in,
                              void* d_out, int out_size)
{
    const float* in = (const float*)d_in[0];
    const float* tg = (const float*)d_in[1];
    float* out = (float*)d_out;

    cudaFuncSetAttribute(qfd_ws,
                         cudaFuncAttributeMaxDynamicSharedMemorySize, SMEM_TOTAL);
    qfd_ws<<<GRID, THREADS, SMEM_TOTAL>>>(in, tg, out);
}

// round 12
// speedup vs baseline: 1.2106x; 1.2106x over previous
#include <cuda_runtime.h>
#include <cstdint>

#define DIM 85
#define B_ROWS 262144
#define TROWS 32
#define THREADS 256                 // 2 independent groups of 128
#define NT (B_ROWS / TROWS)         // 8192 tiles
#define GRID 296                    // 2 persistent CTAs per SM
#define NGROUPS (GRID * 2)          // 592 independent pipelines
#define STAGES 2
#define TILE_F (TROWS * DIM)        // 2720 floats
#define TILE_B (TILE_F * 4)         // 10880 bytes
#define STAGE_B (2 * TILE_B)        // 21760 bytes (in + tg)

// per-group smem block: [mbar 16B][sP 2x128][sT 2x128][sU 2x128][data 2 stages]
#define G_MBAR   0
#define G_SP     16
#define G_ST     (G_SP + 2 * 128 * 4)
#define G_SU     (G_ST + 2 * 128 * 4)
#define G_DATA   (G_SU + 2 * 128 * 4)            // 3088 (16B aligned)
#define GROUP_BYTES (G_DATA + STAGES * STAGE_B)  // 46608
#define SMEM_TOTAL (2 * GROUP_BYTES)             // 93216 -> 2 CTAs/SM

__device__ float g_partials[GRID];
__device__ int   g_count = 0;

__device__ __forceinline__ void mbar_init(uint32_t mbar, uint32_t cnt) {
    asm volatile("mbarrier.init.shared.b64 [%0], %1;" :: "r"(mbar), "r"(cnt) : "memory");
}
__device__ __forceinline__ void mbar_expect_tx(uint32_t mbar, uint32_t bytes) {
    asm volatile("mbarrier.arrive.expect_tx.shared.b64 _, [%0], %1;"
                 :: "r"(mbar), "r"(bytes) : "memory");
}
__device__ __forceinline__ void mbar_wait(uint32_t mbar, uint32_t parity) {
    asm volatile(
        "{\n\t"
        ".reg .pred P;\n\t"
        "W_%=:\n\t"
        "mbarrier.try_wait.parity.acquire.cta.shared::cta.b64 P, [%0], %1, 0x989680;\n\t"
        "@P bra D_%=;\n\t"
        "bra W_%=;\n\t"
        "D_%=:\n\t"
        "}" :: "r"(mbar), "r"(parity) : "memory");
}
__device__ __forceinline__ void bulk_g2s(uint32_t dst, const void* src,
                                         uint32_t bytes, uint32_t mbar) {
    asm volatile(
        "cp.async.bulk.shared::cta.global.mbarrier::complete_tx::bytes [%0], [%1], %2, [%3];"
        :: "r"(dst), "l"(src), "r"(bytes), "r"(mbar) : "memory");
}

__global__ __launch_bounds__(THREADS)
void qfd_grp(const float* __restrict__ in, const float* __restrict__ tg,
             float* __restrict__ out)
{
    extern __shared__ __align__(16) unsigned char smraw[];
    __shared__ float warp_part[THREADS / 32];
    __shared__ bool  s_is_last;

    const int tid  = threadIdx.x;
    const int g    = tid >> 7;                      // group 0/1
    const int ltid = tid & 127;                     // thread within group
    const int lane = tid & 31;
    const int wg   = ltid >> 5;                     // warp within group (0..3)

    unsigned char* gbase = smraw + g * GROUP_BYTES;
    float* sP = (float*)(gbase + G_SP);             // [2][128]
    float* sT = (float*)(gbase + G_ST);
    float* sU = (float*)(gbase + G_SU);
    const uint32_t mb0    = (uint32_t)__cvta_generic_to_shared(gbase + G_MBAR);
    const uint32_t data_s = (uint32_t)__cvta_generic_to_shared(gbase + G_DATA);

    // scan mapping (R9-validated, conflict-free): warp = 32 rows, same segment
    const int row  = ltid & (TROWS - 1);
    const int seg  = wg;                            // 0..3
    const int kbeg = (seg == 0) ? 0 : (1 + 21 * seg);    // 0,22,43,64
    const int kcnt = (seg == 0) ? 22 : 21;
    const float fkbeg = (float)kbeg;
    const int roff = row * DIM + kbeg;

    if (tid == 0) {
#pragma unroll
        for (int gg = 0; gg < 2; gg++) {
            uint32_t m = (uint32_t)__cvta_generic_to_shared(smraw + gg * GROUP_BYTES + G_MBAR);
            mbar_init(m, 1);
            mbar_init(m + 8, 1);
        }
        asm volatile("fence.proxy.async.shared::cta;" ::: "memory");
    }
    __syncthreads();

    const int gidx = blockIdx.x * 2 + g;            // global group id (0..591)

    // ---- prologue: fill both stages ----
    if (ltid == 0) {
#pragma unroll
        for (int s = 0; s < STAGES; s++) {
            int t = gidx + s * NGROUPS;
            if (t < NT) {
                uint32_t mb = mb0 + 8u * s;
                uint32_t ds = data_s + (uint32_t)(s * STAGE_B);
                mbar_expect_tx(mb, STAGE_B);
                bulk_g2s(ds,          in + (size_t)t * TILE_F, TILE_B, mb);
                bulk_g2s(ds + TILE_B, tg + (size_t)t * TILE_F, TILE_B, mb);
            }
        }
    }

    float acc = 0.0f;
    const int barid = 1 + g;

    int k = 0;
    for (int t = gidx; t < NT; t += NGROUPS, k++) {
        const int s  = k & 1;
        const int ph = (k >> 1) & 1;
        const int pp = (k & 1) * 128;               // partials ping-pong
        mbar_wait(mb0 + 8u * s, (uint32_t)ph);

        const float* in_sm = (const float*)(gbase + G_DATA + s * STAGE_B);
        const float* tg_sm = (const float*)(gbase + G_DATA + s * STAGE_B + TILE_B);
        const float* ri = in_sm + roff;
        const float* rt = tg_sm + roff;

        float P = 0.0f, Tn = 0.0f, U = 0.0f;        // Tn = -T
#pragma unroll
        for (int kk = 0; kk < 22; kk++) {
            if (kk < kcnt) {
                float d  = fabsf(ri[kk] - rt[kk]);
                float fk = fkbeg + (float)kk;
                U  = fmaf(d, fmaf(fk, P, Tn), U);
                P += d;
                Tn = fmaf(-fk, d, Tn);
            }
        }
        sP[pp + ltid] = P;
        sT[pp + ltid] = -Tn;
        sU[pp + ltid] = U;

        asm volatile("bar.sync %0, 128;" :: "r"(barid) : "memory");   // group-scope

        // refill stage s with tile t + 2*NGROUPS (all scans of s done)
        if (ltid == 0) {
            int tn = t + STAGES * NGROUPS;
            if (tn < NT) {
                uint32_t mb = mb0 + 8u * s;
                uint32_t ds = data_s + (uint32_t)(s * STAGE_B);
                mbar_expect_tx(mb, STAGE_B);
                bulk_g2s(ds,          in + (size_t)tn * TILE_F, TILE_B, mb);
                bulk_g2s(ds + TILE_B, tg + (size_t)tn * TILE_F, TILE_B, mb);
            }
        }

        // per-row combine, spread over all 4 warps (lanes 0..7, one row each);
        // overlaps next tile's scan — partials are double-buffered.
        if (lane < 8) {
            const int crow = wg * 8 + lane;
            float P0 = sP[pp + 0 * 32 + crow], P1 = sP[pp + 32 + crow];
            float P2 = sP[pp + 64 + crow],    P3 = sP[pp + 96 + crow];
            float T0 = sT[pp + 0 * 32 + crow], T1 = sT[pp + 32 + crow];
            float T2 = sT[pp + 64 + crow],    T3 = sT[pp + 96 + crow];
            float Ut = (sU[pp + crow] + sU[pp + 32 + crow])
                     + (sU[pp + 64 + crow] + sU[pp + 96 + crow]);
            Ut = fmaf(P0, T1, fmaf(-T0, P1, Ut));
            Ut = fmaf(P0, T2, fmaf(-T0, P2, Ut));
            Ut = fmaf(P0, T3, fmaf(-T0, P3, Ut));
            Ut = fmaf(P1, T2, fmaf(-T1, P2, Ut));
            Ut = fmaf(P1, T3, fmaf(-T1, P3, Ut));
            Ut = fmaf(P2, T3, fmaf(-T2, P3, Ut));
            float S = (P0 + P1) + (P2 + P3);
            acc += fmaf(S, S, -(2.0f / (float)DIM) * Ut);
        }
    }

    // ---- deterministic block reduce ----
    __syncthreads();
    for (int o = 16; o; o >>= 1)
        acc += __shfl_down_sync(0xffffffffu, acc, o);
    if (lane == 0)
        warp_part[tid >> 5] = acc;
    __syncthreads();

    if (tid == 0) {
        float sum = 0.0f;
#pragma unroll
        for (int i = 0; i < THREADS / 32; i++)
            sum += warp_part[i];
        g_partials[blockIdx.x] = sum;
        __threadfence();
        int old = atomicAdd(&g_count, 1);
        s_is_last = (old == GRID - 1);
    }
    __syncthreads();

    if (s_is_last) {
        __shared__ double sd[THREADS];
        double a = 0.0;
#pragma unroll
        for (int j = 0; j < (GRID + THREADS - 1) / THREADS; j++) {
            int i = tid + j * THREADS;
            if (i < GRID) a += (double)g_partials[i];
        }
        sd[tid] = a;
        __syncthreads();
        for (int o = THREADS / 2; o; o >>= 1) {
            if (tid < o) sd[tid] += sd[tid + o];
            __syncthreads();
        }
        if (tid == 0) {
            out[0] = (float)(0.1 * sd[0]);
            g_count = 0;                           // self-reset for next replay
        }
    }
}

extern "C" void kernel_launch(void* const* d_in, const int* in_sizes, int n_in,
                              void* d_out, int out_size)
{
    const float* in = (const float*)d_in[0];
    const float* tg = (const float*)d_in[1];
    float* out = (float*)d_out;

    cudaFuncSetAttribute(qfd_grp,
                         cudaFuncAttributeMaxDynamicSharedMemorySize, SMEM_TOTAL);
    qfd_grp<<<GRID, THREADS, SMEM_TOTAL>>>(in, tg, out);
}

// round 13
// speedup vs baseline: 1.3333x; 1.1014x over previous
#include <cuda_runtime.h>
#include <cstdint>

#define DIM 85
#define B_ROWS 262144
#define TROWS 32
#define THREADS 128
#define NT (B_ROWS / TROWS)        // 8192 tiles
#define GRID 592                   // 4 persistent CTAs per SM
#define TILE_F (TROWS * DIM)       // 2720 floats per array per tile
#define TILE_B (TILE_F * 4)        // 10880 bytes
#define STAGE_B (2 * TILE_B)       // 21760 bytes (in + tg)

#define OFF_MBAR 0                 // 2 mbarriers, 8 B each
#define OFF_SP   16
#define OFF_ST   (OFF_SP + THREADS * 4)
#define OFF_SU   (OFF_ST + THREADS * 4)
#define OFF_DATA (OFF_SU + THREADS * 4)          // 1552 -> 16B aligned
#define SMEM_TOTAL (OFF_DATA + 2 * STAGE_B)      // 45072 B -> 4 CTAs/SM

__device__ float g_partials[GRID];
__device__ int   g_count = 0;

__device__ __forceinline__ void mbar_init(uint32_t mbar, uint32_t cnt) {
    asm volatile("mbarrier.init.shared.b64 [%0], %1;" :: "r"(mbar), "r"(cnt) : "memory");
}
__device__ __forceinline__ void mbar_expect_tx(uint32_t mbar, uint32_t bytes) {
    asm volatile("mbarrier.arrive.expect_tx.shared.b64 _, [%0], %1;"
                 :: "r"(mbar), "r"(bytes) : "memory");
}
__device__ __forceinline__ void mbar_wait(uint32_t mbar, uint32_t parity) {
    asm volatile(
        "{\n\t"
        ".reg .pred P;\n\t"
        "W_%=:\n\t"
        "mbarrier.try_wait.parity.acquire.cta.shared::cta.b64 P, [%0], %1, 0x989680;\n\t"
        "@P bra D_%=;\n\t"
        "bra W_%=;\n\t"
        "D_%=:\n\t"
        "}" :: "r"(mbar), "r"(parity) : "memory");
}
__device__ __forceinline__ void bulk_g2s(uint32_t dst, const void* src,
                                         uint32_t bytes, uint32_t mbar) {
    asm volatile(
        "cp.async.bulk.shared::cta.global.mbarrier::complete_tx::bytes [%0], [%1], %2, [%3];"
        :: "r"(dst), "l"(src), "r"(bytes), "r"(mbar) : "memory");
}

__global__ __launch_bounds__(THREADS)
void qfd_tma4c(const float* __restrict__ in, const float* __restrict__ tg,
               float* __restrict__ out)
{
    extern __shared__ __align__(16) unsigned char smraw[];
    float* sP = (float*)(smraw + OFF_SP);
    float* sT = (float*)(smraw + OFF_ST);
    float* sU = (float*)(smraw + OFF_SU);
    __shared__ float warp_part[THREADS / 32];
    __shared__ bool  s_is_last;

    const int tid = threadIdx.x;
    const int row = tid & (TROWS - 1);                     // 0..31
    const int seg = tid >> 5;                              // 0..3 (warp id)
    const int kbeg = (seg == 0) ? 0 : (1 + 21 * seg);      // 0,22,43,64
    const int kcnt = (seg == 0) ? 22 : 21;
    const float fkbeg = (float)kbeg;

    const uint32_t mb0 = (uint32_t)__cvta_generic_to_shared(smraw + OFF_MBAR);
    const uint32_t data_s = (uint32_t)__cvta_generic_to_shared(smraw + OFF_DATA);

    if (tid == 0) {
        mbar_init(mb0, 1);
        mbar_init(mb0 + 8, 1);
        asm volatile("fence.proxy.async.shared::cta;" ::: "memory");
    }
    __syncthreads();

    // ---- prologue: prefetch tiles t0 (stage0) and t0+GRID (stage1) ----
    const int t0 = blockIdx.x;
    if (tid == 0) {
        mbar_expect_tx(mb0, STAGE_B);
        bulk_g2s(data_s,          in + (size_t)t0 * TILE_F, TILE_B, mb0);
        bulk_g2s(data_s + TILE_B, tg + (size_t)t0 * TILE_F, TILE_B, mb0);
        int t1 = t0 + GRID;
        if (t1 < NT) {
            mbar_expect_tx(mb0 + 8, STAGE_B);
            bulk_g2s(data_s + STAGE_B,          in + (size_t)t1 * TILE_F, TILE_B, mb0 + 8);
            bulk_g2s(data_s + STAGE_B + TILE_B, tg + (size_t)t1 * TILE_F, TILE_B, mb0 + 8);
        }
    }

    float acc = 0.0f;

    // ---- per-tile body (stage p, parity ph) — identical shape to R9 ----
    auto process = [&](int t, int p, int ph) {
        mbar_wait(mb0 + 8u * p, (uint32_t)ph);

        const float* in_sm = (const float*)(smraw + OFF_DATA + p * STAGE_B);
        const float* tg_sm = (const float*)(smraw + OFF_DATA + p * STAGE_B + TILE_B);
        const float* ri = in_sm + row * DIM + kbeg;
        const float* rt = tg_sm + row * DIM + kbeg;

        float P = 0.0f, Tn = 0.0f, U = 0.0f;     // Tn = -T
#pragma unroll
        for (int k = 0; k < 22; k++) {
            if (k < kcnt) {
                float d  = fabsf(ri[k] - rt[k]);
                float fk = fkbeg + (float)k;
                U  = fmaf(d, fmaf(fk, P, Tn), U);
                P += d;
                Tn = fmaf(-fk, d, Tn);
            }
        }
        sP[tid] = P; sT[tid] = -Tn; sU[tid] = U;
        __syncthreads();                          // stage p fully consumed

        // refill stage p with tile t + 2*GRID (decoupled TMA stream)
        int tn = t + 2 * GRID;
        if (tid == 0 && tn < NT) {
            uint32_t mb = mb0 + 8u * p;
            uint32_t ds = data_s + (uint32_t)(p * STAGE_B);
            mbar_expect_tx(mb, STAGE_B);
            bulk_g2s(ds,          in + (size_t)tn * TILE_F, TILE_B, mb);
            bulk_g2s(ds + TILE_B, tg + (size_t)tn * TILE_F, TILE_B, mb);
        }

        // per-row combine of 4 segment partials (threads 0..31)
        if (tid < TROWS) {
            float P0 = sP[tid], P1 = sP[32 + tid], P2 = sP[64 + tid], P3 = sP[96 + tid];
            float T0 = sT[tid], T1 = sT[32 + tid], T2 = sT[64 + tid], T3 = sT[96 + tid];
            float Ut = (sU[tid] + sU[32 + tid]) + (sU[64 + tid] + sU[96 + tid]);
            Ut = fmaf(P0, T1, fmaf(-T0, P1, Ut));
            Ut = fmaf(P0, T2, fmaf(-T0, P2, Ut));
            Ut = fmaf(P0, T3, fmaf(-T0, P3, Ut));
            Ut = fmaf(P1, T2, fmaf(-T1, P2, Ut));
            Ut = fmaf(P1, T3, fmaf(-T1, P3, Ut));
            Ut = fmaf(P2, T3, fmaf(-T2, P3, Ut));
            float S = (P0 + P1) + (P2 + P3);
            acc += fmaf(S, S, -(2.0f / (float)DIM) * Ut);
        }
        __syncthreads();                          // protect sP/sT/sU reuse
    };

    int ph0 = 0, ph1 = 0;
    int t = t0;
    while (t < NT) {
        process(t, 0, ph0); ph0 ^= 1;
        t += GRID;
        if (t >= NT) break;
        process(t, 1, ph1); ph1 ^= 1;
        t += GRID;
    }

    // ---- block reduce per-thread accumulators (deterministic) ----
    for (int o = 16; o; o >>= 1)
        acc += __shfl_down_sync(0xffffffffu, acc, o);
    if ((tid & 31) == 0)
        warp_part[tid >> 5] = acc;
    __syncthreads();

    if (tid == 0) {
        float s = 0.0f;
#pragma unroll
        for (int i = 0; i < THREADS / 32; i++)
            s += warp_part[i];
        g_partials[blockIdx.x] = s;
        __threadfence();
        int old = atomicAdd(&g_count, 1);
        s_is_last = (old == GRID - 1);
    }
    __syncthreads();

    // ---- last-arriving block: final deterministic reduce in double ----
    if (s_is_last) {
        __shared__ double sd[THREADS];
        double a = 0.0;
#pragma unroll
        for (int j = 0; j < (GRID + THREADS - 1) / THREADS; j++) {
            int i = tid + j * THREADS;
            if (i < GRID) a += (double)g_partials[i];
        }
        sd[tid] = a;
        __syncthreads();
        for (int o = THREADS / 2; o; o >>= 1) {
            if (tid < o) sd[tid] += sd[tid + o];
            __syncthreads();
        }
        if (tid == 0) {
            out[0] = (float)(0.1 * sd[0]);
            g_count = 0;                          // self-reset for next replay
        }
    }
}

extern "C" void kernel_launch(void* const* d_in, const int* in_sizes, int n_in,
                              void* d_out, int out_size)
{
    const float* in = (const float*)d_in[0];
    const float* tg = (const float*)d_in[1];
    float* out = (float*)d_out;

    cudaFuncSetAttribute(qfd_tma4c,
                         cudaFuncAttributeMaxDynamicSharedMemorySize, SMEM_TOTAL);
    qfd_tma4c<<<GRID, THREADS, SMEM_TOTAL>>>(in, tg, out);
}